// round 4
// baseline (speedup 1.0000x reference)
#include <cuda_runtime.h>
#include <math.h>

#define NF 16          // B*S
#define AA 24000
#define CC 80
#define MM 20
#define CE 7
#define TA 64          // anchors per block in main kernel
#define K1B 24         // blocks_x in match kernel
#define K3BLKS (AA / TA * NF)   // 6000

// ---- device scratch (no allocations; .bss zero-init; finalize resets what it uses) ----
__device__ unsigned long long g_gt_part[NF * K1B * MM];
__device__ double             g_cls_sum;
__device__ double             g_reg_sum;
__device__ int                g_pos_cnt;
__device__ unsigned           g_done;
__device__ float              g_w[CC];

__device__ __forceinline__ float ex2f(float x){ float y; asm("ex2.approx.f32 %0,%1;":"=f"(y):"f"(x)); return y; }
__device__ __forceinline__ float lg2f(float x){ float y; asm("lg2.approx.f32 %0,%1;":"=f"(y):"f"(x)); return y; }
__device__ __forceinline__ float rcpf(float x){ float y; asm("rcp.approx.f32 %0,%1;":"=f"(y):"f"(x)); return y; }

// ---------------- K1: per-gt best anchor (partial per block) + CB weights ------
__global__ void __launch_bounds__(256) k1_match(const float* __restrict__ gt_boxes,
                                                const int* __restrict__ counts,
                                                const float* __restrict__ anchors,
                                                const int* __restrict__ cls_num_list) {
    int f = blockIdx.y;
    int tid = threadIdx.x;
    int lane = tid & 31, wrp = tid >> 5;
    __shared__ float4 sgtb[MM];
    __shared__ float  sga[MM];
    __shared__ unsigned long long skey_s[8][MM];
    __shared__ float  sraw[256];
    if (tid < MM) {
        float4 b = ((const float4*)gt_boxes)[f * MM + tid];
        sgtb[tid] = b;
        sga[tid] = (b.z - b.x) * (b.w - b.y);
    }
    __syncthreads();
    int count = counts[f]; if (count > MM) count = MM;

    float    bI[MM];
    unsigned bX[MM];
#pragma unroll
    for (int m = 0; m < MM; m++) { bI[m] = -1.f; bX[m] = 0; }

    for (int a = blockIdx.x * 256 + tid; a < AA; a += K1B * 256) {
        float4 an = ((const float4*)anchors)[a];
        float ax1 = an.x - 0.5f * an.z, ay1 = an.y - 0.5f * an.w;
        float ax2 = an.x + 0.5f * an.z, ay2 = an.y + 0.5f * an.w;
        float sa = an.z * an.w;
#pragma unroll
        for (int m = 0; m < MM; m++) {
            if (m < count) {
                float4 b = sgtb[m];
                float lx = fmaxf(ax1, b.x), ly = fmaxf(ay1, b.y);
                float rx = fminf(ax2, b.z), ry = fminf(ay2, b.w);
                float w = fmaxf(rx - lx, 0.f), h = fmaxf(ry - ly, 0.f);
                float inter = w * h;
                float uni = sa + sga[m] - inter;
                if (inter > bI[m] * uni) {            // strict >: first anchor wins ties
                    bI[m] = inter / (uni + 1e-10f);
                    bX[m] = (unsigned)a;
                }
            }
        }
    }

    // per-gt best anchor within block: warp shuffle max on packed (iou_bits, ~idx)
#pragma unroll
    for (int m = 0; m < MM; m++) {
        unsigned long long key = 0ull;
        if (m < count && bI[m] >= 0.f) {
            key = ((unsigned long long)__float_as_uint(bI[m]) << 32) |
                  (unsigned long long)(0xFFFFFFFFu - bX[m]);   // smaller idx wins ties
        }
#pragma unroll
        for (int o = 16; o > 0; o >>= 1) {
            unsigned long long other = __shfl_down_sync(0xffffffffu, key, o);
            if (other > key) key = other;
        }
        if (lane == 0) skey_s[wrp][m] = key;
    }
    __syncthreads();
    if (tid < MM) {
        unsigned long long k = skey_s[0][tid];
#pragma unroll
        for (int w = 1; w < 8; w++) { unsigned long long o = skey_s[w][tid]; if (o > k) k = o; }
        g_gt_part[((size_t)f * K1B + blockIdx.x) * MM + tid] = k;   // race-free, no init needed
    }

    // block (0,0): class-balance weights (overlapped with the other 383 blocks)
    if (blockIdx.x == 0 && blockIdx.y == 0) {
        float raw = 0.f;
        if (tid < CC) {
            double beta = (double)0.9999f;
            double n = (double)cls_num_list[tid];
            raw = (float)((1.0 - beta) / (1.0 - pow(beta, n)));
        }
        sraw[tid] = raw;
        __syncthreads();
        for (int s = 128; s > 0; s >>= 1) {
            if (tid < s) sraw[tid] += sraw[tid + s];
            __syncthreads();
        }
        if (tid < CC) g_w[tid] = raw / sraw[0];
    }
}

// ---------------- K3: main loss + inline match decode + last-block finalize ----
__global__ void __launch_bounds__(256) k3_main(const float* __restrict__ confidence,
                                               const float* __restrict__ pred_loc,
                                               const float* __restrict__ gt_boxes,
                                               const float* __restrict__ gt_labels,
                                               const int* __restrict__ counts,
                                               const float* __restrict__ anchors,
                                               const float* __restrict__ ego_preds,
                                               const int* __restrict__ ego_labels,
                                               float* __restrict__ out, int out_size) {
    int f = blockIdx.y;
    int ab = blockIdx.x * TA;
    int tid = threadIdx.x;
    int lane = tid & 31, wrp = tid >> 5;

    __shared__ unsigned labm_s[MM * 3];   // 80-class bitmask per gt
    __shared__ float  w_s[CC];
    __shared__ int    meta_s[TA];
    __shared__ int    sidx_s[MM];         // forced (best) anchor per gt
    __shared__ float4 gtb_s[MM];
    __shared__ float  sga_s[MM];
    __shared__ float  redc[8], redr[8], redp[8];
    __shared__ int    sflag;
    __shared__ float  col_s[CE];
    __shared__ int    nval_s;

    int count = counts[f]; if (count > MM) count = MM;

    // label bitmasks via ballot (coalesced 32-wide reads)
    const float* gl = gt_labels + (size_t)f * MM * CC;
    for (int m = wrp; m < MM; m += 8) {
        unsigned b0 = __ballot_sync(0xffffffffu, gl[m * CC + lane] > 0.5f);
        unsigned b1 = __ballot_sync(0xffffffffu, gl[m * CC + 32 + lane] > 0.5f);
        unsigned b2 = __ballot_sync(0xffffffffu, (lane < (CC - 64)) ? (gl[m * CC + 64 + lane] > 0.5f) : false);
        if (lane == 0) { labm_s[m * 3] = b0; labm_s[m * 3 + 1] = b1; labm_s[m * 3 + 2] = b2; }
    }
    if (tid < CC) w_s[tid] = g_w[tid];
    if (tid < MM) {
        float4 b = ((const float4*)gt_boxes)[f * MM + tid];
        gtb_s[tid] = b;
        sga_s[tid] = (b.z - b.x) * (b.w - b.y);
        int sidx = -1;
        if (tid < count) {
            unsigned long long key = g_gt_part[(size_t)f * K1B * MM + tid];
#pragma unroll
            for (int bb = 1; bb < K1B; bb++) {
                unsigned long long o = g_gt_part[((size_t)f * K1B + bb) * MM + tid];
                if (o > key) key = o;
            }
            sidx = (int)(0xFFFFFFFFu - (unsigned)(key & 0xFFFFFFFFull));
        }
        sidx_s[tid] = sidx;
    }
    __syncthreads();

    float myreg = 0.f, mypos = 0.f;
    if (tid < TA) {
        int a = ab + tid;
        int meta = -1;
        float4 an = ((const float4*)anchors)[a];
        if (count > 0) {
            // recompute this anchor's best gt (cheap: <=20 IoUs)
            float ax1 = an.x - 0.5f * an.z, ay1 = an.y - 0.5f * an.w;
            float ax2 = an.x + 0.5f * an.z, ay2 = an.y + 0.5f * an.w;
            float sa = an.z * an.w;
            float aB = -1.f; int aM = 0;
            for (int m = 0; m < count; m++) {
                float4 b = gtb_s[m];
                float lx = fmaxf(ax1, b.x), ly = fmaxf(ay1, b.y);
                float rx = fminf(ax2, b.z), ry = fminf(ay2, b.w);
                float w = fmaxf(rx - lx, 0.f), h = fmaxf(ry - ly, 0.f);
                float inter = w * h;
                float uni = sa + sga_s[m] - inter;
                if (inter > aB * uni) { aB = inter / (uni + 1e-10f); aM = m; }
            }
            meta = (aB < 0.4f) ? -2 : ((aB < 0.5f) ? -1 : aM);
            for (int m = 0; m < count; m++)        // ascending: last write wins (ref scatter)
                if (sidx_s[m] == a) meta = m;
        }
        meta_s[tid] = meta;
        if (meta >= 0) {
            mypos = 1.f;
            float4 b = gtb_s[meta];
            float lcx = ((b.x + b.z) * 0.5f - an.x) / (0.1f * an.z);
            float lcy = ((b.y + b.w) * 0.5f - an.y) / (0.1f * an.w);
            float lw = logf(fmaxf(b.z - b.x, 1e-6f) / an.z) * 5.0f;
            float lh = logf(fmaxf(b.w - b.y, 1e-6f) / an.w) * 5.0f;
            float4 pl = ((const float4*)pred_loc)[f * AA + a];
            float n0 = fabsf(pl.x - lcx), n1 = fabsf(pl.y - lcy);
            float n2 = fabsf(pl.z - lw),  n3 = fabsf(pl.w - lh);
            const float SB = 1.f / 9.f;
            myreg  = (n0 < SB ? 4.5f * n0 * n0 : n0 - 0.5f * SB);
            myreg += (n1 < SB ? 4.5f * n1 * n1 : n1 - 0.5f * SB);
            myreg += (n2 < SB ? 4.5f * n2 * n2 : n2 - 0.5f * SB);
            myreg += (n3 < SB ? 4.5f * n3 * n3 : n3 - 0.5f * SB);
        }
    }
    __syncthreads();

    // ---- hot loop: TA anchors x 80 classes as float4, unified focal math ----
    //   t = x*log2e, u = 2^t, v = 1+u, s = lg2(v), r = 1/v
    //   neg: ln2*s*(1-r)*1e-4     pos: w * ln2*(s-t)*r
    const float4* c4 = (const float4*)(confidence + ((size_t)f * AA + ab) * CC);
    const float L2E = 1.4426950408889634f;
    const float LN2 = 0.6931471805599453f;
    float nacc = 0.f, pacc = 0.f;
#pragma unroll
    for (int it = 0; it < (TA * CC / 4) / 256; it++) {   // 5 iters
        int e = it * 256 + tid;                           // < 1280
        int a_l = (int)(((unsigned)e * 52429u) >> 20);    // e / 20
        int cbase = (e - a_l * 20) * 4;
        int m = meta_s[a_l];
        if (m != -1) {
            float4 x4 = __ldcs(c4 + e);
            unsigned mbits = 0u;
            if (m >= 0) mbits = (labm_s[m * 3 + (cbase >> 5)] >> (cbase & 31)) & 0xFu;
            float xs[4] = {x4.x, x4.y, x4.z, x4.w};
#pragma unroll
            for (int j = 0; j < 4; j++) {
                float x = xs[j];
                float t = x * L2E;
                float u = ex2f(t);
                float v = 1.f + u;
                float s = lg2f(v);
                float r = rcpf(v);
                if ((mbits >> j) & 1) pacc = fmaf(w_s[cbase + j] * (s - t), r, pacc);
                else                  nacc = fmaf(s, 1.f - r, nacc);
            }
        }
    }
    const float CB1M = 1.0f - 0.9999f;
    float csum = LN2 * fmaf(CB1M, nacc, pacc);

    // ---- block reductions via shuffles, one atomic each ----
#pragma unroll
    for (int o = 16; o > 0; o >>= 1) {
        csum  += __shfl_down_sync(0xffffffffu, csum, o);
        myreg += __shfl_down_sync(0xffffffffu, myreg, o);
        mypos += __shfl_down_sync(0xffffffffu, mypos, o);
    }
    if (lane == 0) { redc[wrp] = csum; redr[wrp] = myreg; redp[wrp] = mypos; }
    __syncthreads();
    if (tid == 0) {
        float c = 0.f, r = 0.f, p = 0.f;
#pragma unroll
        for (int w = 0; w < 8; w++) { c += redc[w]; r += redr[w]; p += redp[w]; }
        atomicAdd(&g_cls_sum, (double)c);
        if (r != 0.f) atomicAdd(&g_reg_sum, (double)r);
        if (p != 0.f) atomicAdd(&g_pos_cnt, (int)(p + 0.5f));
    }

    // ---- last-block finalize: ego focal + output + accumulator reset ----
    __threadfence();
    if (tid == 0) {
        unsigned d = atomicAdd(&g_done, 1u);
        sflag = (d == (unsigned)(K3BLKS - 1));
    }
    __syncthreads();
    if (sflag) {
        if (tid < CE) col_s[tid] = 0.f;
        if (tid == 0) nval_s = 0;
        __syncthreads();
        if (tid < NF) {
            int l = ego_labels[tid];
            if (l > -1) { atomicAdd(&nval_s, 1); if (l < CE) col_s[l] = 1.f; }
        }
        __syncthreads();
        float term = 0.f;
        if (tid < NF * CE) {
            int i = tid / CE, c = tid - i * CE;
            if (ego_labels[i] > -1) {
                float x = ego_preds[tid];
                float ep = 1.f / (1.f + expf(-x));
                ep = fminf(fmaxf(ep, 1e-7f), 1.f - 1e-7f);
                float oh = col_s[c];
                float af = 0.25f * oh + 0.75f * (1.f - oh);
                float pt = ep * oh + (1.f - ep) * (1.f - oh);
                float bce = -(oh * logf(ep) + (1.f - oh) * log1pf(-ep));
                float omp = 1.f - pt;
                term = bce * af * omp * omp;
            }
        }
#pragma unroll
        for (int o = 16; o > 0; o >>= 1) term += __shfl_down_sync(0xffffffffu, term, o);
        if (lane == 0) redc[wrp] = term;
        __syncthreads();
        if (tid == 0) {
            float esum = redc[0] + redc[1] + redc[2] + redc[3];
            int nval = nval_s;
            float ego = (nval > 0) ? esum / fmaxf((float)nval, 1.f) : 0.f;
            double cs = *((volatile double*)&g_cls_sum);
            double rs = *((volatile double*)&g_reg_sum);
            int pc = *((volatile int*)&g_pos_cnt);
            float np = fmaxf(1.f, (float)pc);
            float reg = (float)rs / (np * 4.f);
            float cls = (float)cs / np;
            if (out_size > 0) out[0] = reg;
            if (out_size > 1) out[1] = cls * 0.125f + ego * 0.25f;
            // reset for next graph replay (deterministic across calls)
            g_cls_sum = 0.0;
            g_reg_sum = 0.0;
            g_pos_cnt = 0;
            __threadfence();
            g_done = 0;
        }
    }
}

extern "C" void kernel_launch(void* const* d_in, const int* in_sizes, int n_in,
                              void* d_out, int out_size) {
    (void)in_sizes; (void)n_in;
    const float* confidence   = (const float*)d_in[0];
    const float* pred_loc     = (const float*)d_in[1];
    const float* gt_boxes     = (const float*)d_in[2];
    const float* gt_labels    = (const float*)d_in[3];
    const int*   counts       = (const int*)d_in[4];
    const float* anchors      = (const float*)d_in[5];
    const float* ego_preds    = (const float*)d_in[6];
    const int*   ego_labels   = (const int*)d_in[7];
    const int*   cls_num_list = (const int*)d_in[8];
    float* out = (float*)d_out;

    k1_match<<<dim3(K1B, NF), 256>>>(gt_boxes, counts, anchors, cls_num_list);
    k3_main<<<dim3(AA / TA, NF), 256>>>(confidence, pred_loc, gt_boxes, gt_labels,
                                        counts, anchors, ego_preds, ego_labels, out, out_size);
}

// round 6
// speedup vs baseline: 1.3646x; 1.3646x over previous
#include <cuda_runtime.h>
#include <math.h>

#define NF 16          // B*S
#define AA 24000
#define CC 80
#define MM 20
#define CE 7
#define TA 240         // anchors per block in main kernel
#define K3GX (AA / TA) // 100
#define K3BLKS (K3GX * NF)      // 1600
#define K1B 24         // blocks_x in match kernel

// ---- device scratch (no allocations; .bss zero-init; finalize resets g_gt_key etc.) ----
__device__ unsigned long long g_gt_key[NF * MM];
__device__ signed char        g_meta[NF * AA];     // signed: aarch64 plain char is unsigned!
__device__ unsigned           g_labm[NF * MM * 3];
__device__ float              g_w[CC];
__device__ double             g_cls_sum;
__device__ double             g_reg_sum;
__device__ int                g_pos_cnt;
__device__ unsigned           g_done;

__device__ __forceinline__ float ex2f(float x){ float y; asm("ex2.approx.f32 %0,%1;":"=f"(y):"f"(x)); return y; }
__device__ __forceinline__ float lg2f(float x){ float y; asm("lg2.approx.f32 %0,%1;":"=f"(y):"f"(x)); return y; }
__device__ __forceinline__ float rcpf(float x){ float y; asm("rcp.approx.f32 %0,%1;":"=f"(y):"f"(x)); return y; }

// ---------------- K1: full match precompute ----------------
// Writes: g_meta (per-anchor class {-2 bg, -1 ignore, m pos}), g_gt_key (per-gt best
// anchor via atomicMax on packed key), g_labm (label bitmasks), g_w (CB weights).
__global__ void __launch_bounds__(256) k1_match(const float* __restrict__ gt_boxes,
                                                const int* __restrict__ counts,
                                                const float* __restrict__ anchors,
                                                const int* __restrict__ cls_num_list,
                                                const float* __restrict__ gt_labels) {
    int f = blockIdx.y;
    int tid = threadIdx.x;
    int lane = tid & 31, wrp = tid >> 5;
    __shared__ float4 sgtb[MM];
    __shared__ float  sga[MM];
    __shared__ unsigned long long skey_s[8][MM];
    __shared__ float  sraw[256];
    if (tid < MM) {
        float4 b = ((const float4*)gt_boxes)[f * MM + tid];
        sgtb[tid] = b;
        sga[tid] = (b.z - b.x) * (b.w - b.y);
    }
    __syncthreads();
    int count = counts[f]; if (count > MM) count = MM;

    float    bI[MM];
    unsigned bX[MM];
#pragma unroll
    for (int m = 0; m < MM; m++) { bI[m] = -1.f; bX[m] = 0; }

    for (int a = blockIdx.x * 256 + tid; a < AA; a += K1B * 256) {
        float4 an = ((const float4*)anchors)[a];
        float ax1 = an.x - 0.5f * an.z, ay1 = an.y - 0.5f * an.w;
        float ax2 = an.x + 0.5f * an.z, ay2 = an.y + 0.5f * an.w;
        float sa = an.z * an.w;
        float aB = -1.f;
        int   aM = 0;
#pragma unroll
        for (int m = 0; m < MM; m++) {
            if (m < count) {
                float4 b = sgtb[m];
                float lx = fmaxf(ax1, b.x), ly = fmaxf(ay1, b.y);
                float rx = fminf(ax2, b.z), ry = fminf(ay2, b.w);
                float w = fmaxf(rx - lx, 0.f), h = fmaxf(ry - ly, 0.f);
                float inter = w * h;
                float uni = sa + sga[m] - inter;
                // rational argmax: divide only on improvement; strict > = first-index tie
                bool upA = inter > aB * uni;
                bool upG = inter > bI[m] * uni;
                if (upA | upG) {
                    float q = inter / (uni + 1e-10f);
                    if (upA) { aB = q; aM = m; }
                    if (upG) { bI[m] = q; bX[m] = (unsigned)a; }
                }
            }
        }
        int meta = (count == 0) ? -1 : ((aB < 0.4f) ? -2 : ((aB < 0.5f) ? -1 : aM));
        g_meta[f * AA + a] = (signed char)meta;
    }

    // per-gt best anchor: warp shuffle max on packed (iou_bits, ~idx), then atomicMax
#pragma unroll
    for (int m = 0; m < MM; m++) {
        unsigned long long key = 0ull;
        if (m < count && bI[m] >= 0.f) {
            key = ((unsigned long long)__float_as_uint(bI[m]) << 32) |
                  (unsigned long long)(0xFFFFFFFFu - bX[m]);   // smaller idx wins ties
        }
#pragma unroll
        for (int o = 16; o > 0; o >>= 1) {
            unsigned long long other = __shfl_down_sync(0xffffffffu, key, o);
            if (other > key) key = other;
        }
        if (lane == 0) skey_s[wrp][m] = key;
    }
    __syncthreads();
    if (tid < MM) {
        unsigned long long k = skey_s[0][tid];
#pragma unroll
        for (int w = 1; w < 8; w++) { unsigned long long o = skey_s[w][tid]; if (o > k) k = o; }
        if (k) atomicMax(&g_gt_key[f * MM + tid], k);
    }

    if (blockIdx.x == 0) {
        // label bitmasks for this frame (once per frame, not once per k3 block)
        const float* gl = gt_labels + (size_t)f * MM * CC;
        for (int m = wrp; m < MM; m += 8) {
            unsigned b0 = __ballot_sync(0xffffffffu, gl[m * CC + lane] > 0.5f);
            unsigned b1 = __ballot_sync(0xffffffffu, gl[m * CC + 32 + lane] > 0.5f);
            unsigned b2 = __ballot_sync(0xffffffffu, (lane < (CC - 64)) ? (gl[m * CC + 64 + lane] > 0.5f) : false);
            if (lane == 0) {
                g_labm[(f * MM + m) * 3]     = b0;
                g_labm[(f * MM + m) * 3 + 1] = b1;
                g_labm[(f * MM + m) * 3 + 2] = b2;
            }
        }
        // class-balance weights (block (0,0) only)
        if (f == 0) {
            float raw = 0.f;
            if (tid < CC) {
                double beta = (double)0.9999f;
                double n = (double)cls_num_list[tid];
                raw = (float)((1.0 - beta) / (1.0 - pow(beta, n)));
            }
            sraw[tid] = raw;
            __syncthreads();
            for (int s = 128; s > 0; s >>= 1) {
                if (tid < s) sraw[tid] += sraw[tid + s];
                __syncthreads();
            }
            if (tid < CC) g_w[tid] = raw / sraw[0];
        }
    }
}

// ---------------- K3: loss accumulation + last-block finalize ----------------
__global__ void __launch_bounds__(256) k3_main(const float* __restrict__ confidence,
                                               const float* __restrict__ pred_loc,
                                               const float* __restrict__ gt_boxes,
                                               const int* __restrict__ counts,
                                               const float* __restrict__ anchors,
                                               const float* __restrict__ ego_preds,
                                               const int* __restrict__ ego_labels,
                                               float* __restrict__ out, int out_size) {
    int f = blockIdx.y;
    int ab = blockIdx.x * TA;
    int tid = threadIdx.x;
    int lane = tid & 31, wrp = tid >> 5;

    __shared__ unsigned labm_s[MM * 3];
    __shared__ float  w_s[CC];
    __shared__ signed char meta_s[TA];
    __shared__ int    sidx_s[MM];
    __shared__ float4 gtb_s[MM];
    __shared__ float  redc[8], redr[8], redp[8];
    __shared__ int    sflag;
    __shared__ float  col_s[CE];
    __shared__ int    nval_s;

    int count = counts[f]; if (count > MM) count = MM;

    if (tid < MM * 3) labm_s[tid] = g_labm[f * MM * 3 + tid];
    if (tid < CC) w_s[tid] = g_w[tid];
    if (tid < MM) {
        gtb_s[tid] = ((const float4*)gt_boxes)[f * MM + tid];
        int sidx = -1;
        if (tid < count) {
            unsigned long long key = g_gt_key[f * MM + tid];
            sidx = (int)(0xFFFFFFFFu - (unsigned)(key & 0xFFFFFFFFull));
        }
        sidx_s[tid] = sidx;
    }
    int meta = -1;
    if (tid < TA) meta = (int)g_meta[f * AA + ab + tid];
    __syncthreads();

    float myreg = 0.f, mypos = 0.f;
    if (tid < TA) {
        int a = ab + tid;
        for (int m = 0; m < count; m++)          // ascending: last write wins (ref scatter)
            if (sidx_s[m] == a) meta = m;
        meta_s[tid] = (signed char)meta;
        if (meta >= 0) {
            mypos = 1.f;
            float4 an = ((const float4*)anchors)[a];
            float4 b = gtb_s[meta];
            float lcx = ((b.x + b.z) * 0.5f - an.x) / (0.1f * an.z);
            float lcy = ((b.y + b.w) * 0.5f - an.y) / (0.1f * an.w);
            float lw = logf(fmaxf(b.z - b.x, 1e-6f) / an.z) * 5.0f;
            float lh = logf(fmaxf(b.w - b.y, 1e-6f) / an.w) * 5.0f;
            float4 pl = ((const float4*)pred_loc)[f * AA + a];
            float n0 = fabsf(pl.x - lcx), n1 = fabsf(pl.y - lcy);
            float n2 = fabsf(pl.z - lw),  n3 = fabsf(pl.w - lh);
            const float SB = 1.f / 9.f;
            myreg  = (n0 < SB ? 4.5f * n0 * n0 : n0 - 0.5f * SB);
            myreg += (n1 < SB ? 4.5f * n1 * n1 : n1 - 0.5f * SB);
            myreg += (n2 < SB ? 4.5f * n2 * n2 : n2 - 0.5f * SB);
            myreg += (n3 < SB ? 4.5f * n3 * n3 : n3 - 0.5f * SB);
        }
    }
    __syncthreads();

    // ---- hot loop: TA anchors x 80 classes as float4 ----
    //   t = x*log2e, u = 2^t, v = 1+u, s = lg2(v), r = 1/v
    //   neg: ln2*s*(1-r)*1e-4     pos: w * ln2*(s-t)*r
    const float4* c4 = (const float4*)(confidence + ((size_t)f * AA + ab) * CC);
    const float L2E = 1.4426950408889634f;
    const float LN2 = 0.6931471805599453f;
    float nacc = 0.f, pacc = 0.f;
    for (int e = tid; e < TA * CC / 4; e += 256) {        // 4800 groups
        int a_l = (int)(((unsigned)e * 52429u) >> 20);    // e / 20
        int cbase = (e - a_l * 20) * 4;
        int m = (int)meta_s[a_l];
        if (m != -1) {
            float4 x4 = __ldcs(c4 + e);
            unsigned mbits = 0u;
            if (m >= 0) mbits = (labm_s[m * 3 + (cbase >> 5)] >> (cbase & 31)) & 0xFu;
            float xs[4] = {x4.x, x4.y, x4.z, x4.w};
#pragma unroll
            for (int j = 0; j < 4; j++) {
                float x = xs[j];
                float t = x * L2E;
                float u = ex2f(t);
                float v = 1.f + u;
                float s = lg2f(v);
                float r = rcpf(v);
                if ((mbits >> j) & 1) pacc = fmaf(w_s[cbase + j] * (s - t), r, pacc);
                else                  nacc = fmaf(s, 1.f - r, nacc);
            }
        }
    }
    const float CB1M = 1.0f - 0.9999f;
    float csum = LN2 * fmaf(CB1M, nacc, pacc);

    // ---- block reductions via shuffles, one atomic each ----
#pragma unroll
    for (int o = 16; o > 0; o >>= 1) {
        csum  += __shfl_down_sync(0xffffffffu, csum, o);
        myreg += __shfl_down_sync(0xffffffffu, myreg, o);
        mypos += __shfl_down_sync(0xffffffffu, mypos, o);
    }
    if (lane == 0) { redc[wrp] = csum; redr[wrp] = myreg; redp[wrp] = mypos; }
    __syncthreads();
    if (tid == 0) {
        float c = 0.f, r = 0.f, p = 0.f;
#pragma unroll
        for (int w = 0; w < 8; w++) { c += redc[w]; r += redr[w]; p += redp[w]; }
        atomicAdd(&g_cls_sum, (double)c);
        if (r != 0.f) atomicAdd(&g_reg_sum, (double)r);
        if (p != 0.f) atomicAdd(&g_pos_cnt, (int)(p + 0.5f));
    }

    // ---- last-block finalize: ego focal + output + accumulator reset ----
    __threadfence();
    if (tid == 0) {
        unsigned d = atomicAdd(&g_done, 1u);
        sflag = (d == (unsigned)(K3BLKS - 1));
    }
    __syncthreads();
    if (sflag) {
        if (tid < CE) col_s[tid] = 0.f;
        if (tid == 0) nval_s = 0;
        __syncthreads();
        if (tid < NF) {
            int l = ego_labels[tid];
            if (l > -1) { atomicAdd(&nval_s, 1); if (l < CE) col_s[l] = 1.f; }
        }
        __syncthreads();
        float term = 0.f;
        if (tid < NF * CE) {
            int i = tid / CE, c = tid - i * CE;
            if (ego_labels[i] > -1) {
                float x = ego_preds[tid];
                float ep = 1.f / (1.f + expf(-x));
                ep = fminf(fmaxf(ep, 1e-7f), 1.f - 1e-7f);
                float oh = col_s[c];
                float af = 0.25f * oh + 0.75f * (1.f - oh);
                float pt = ep * oh + (1.f - ep) * (1.f - oh);
                float bce = -(oh * logf(ep) + (1.f - oh) * log1pf(-ep));
                float omp = 1.f - pt;
                term = bce * af * omp * omp;
            }
        }
#pragma unroll
        for (int o = 16; o > 0; o >>= 1) term += __shfl_down_sync(0xffffffffu, term, o);
        if (lane == 0) redc[wrp] = term;
        __syncthreads();
        if (tid == 0) {
            float esum = redc[0] + redc[1] + redc[2] + redc[3];
            int nval = nval_s;
            float ego = (nval > 0) ? esum / fmaxf((float)nval, 1.f) : 0.f;
            double cs = *((volatile double*)&g_cls_sum);
            double rs = *((volatile double*)&g_reg_sum);
            int pc = *((volatile int*)&g_pos_cnt);
            float np = fmaxf(1.f, (float)pc);
            float reg = (float)rs / (np * 4.f);
            float cls = (float)cs / np;
            if (out_size > 0) out[0] = reg;
            if (out_size > 1) out[1] = cls * 0.125f + ego * 0.25f;
            // reset for next graph replay
            g_cls_sum = 0.0;
            g_reg_sum = 0.0;
            g_pos_cnt = 0;
        }
        // reset per-gt keys (atomicMax target) for next replay
        for (int i = tid; i < NF * MM; i += 256) g_gt_key[i] = 0ull;
        __syncthreads();
        if (tid == 0) { __threadfence(); g_done = 0; }
    }
}

extern "C" void kernel_launch(void* const* d_in, const int* in_sizes, int n_in,
                              void* d_out, int out_size) {
    (void)in_sizes; (void)n_in;
    const float* confidence   = (const float*)d_in[0];
    const float* pred_loc     = (const float*)d_in[1];
    const float* gt_boxes     = (const float*)d_in[2];
    const float* gt_labels    = (const float*)d_in[3];
    const int*   counts       = (const int*)d_in[4];
    const float* anchors      = (const float*)d_in[5];
    const float* ego_preds    = (const float*)d_in[6];
    const int*   ego_labels   = (const int*)d_in[7];
    const int*   cls_num_list = (const int*)d_in[8];
    float* out = (float*)d_out;

    k1_match<<<dim3(K1B, NF), 256>>>(gt_boxes, counts, anchors, cls_num_list, gt_labels);
    k3_main<<<dim3(K3GX, NF), 256>>>(confidence, pred_loc, gt_boxes, counts, anchors,
                                     ego_preds, ego_labels, out, out_size);
}

// round 7
// speedup vs baseline: 1.3698x; 1.0038x over previous
#include <cuda_runtime.h>
#include <math.h>

#define NF 16          // B*S
#define AA 24000
#define CC 80
#define MM 20
#define CE 7
#define TA 240         // anchors per block in main kernel
#define K3GX (AA / TA) // 100
#define K3BLKS (K3GX * NF)      // 1600
#define K1B 24         // blocks_x in match kernel

// ---- device scratch (no allocations; .bss zero-init; finalize resets g_gt_key etc.) ----
__device__ unsigned long long g_gt_key[NF * MM];
__device__ signed char        g_meta[NF * AA];     // signed: aarch64 plain char is unsigned!
__device__ unsigned           g_labm[NF * MM * 3];
__device__ float              g_w[CC];
__device__ double             g_cls_sum;
__device__ double             g_reg_sum;
__device__ int                g_pos_cnt;
__device__ unsigned           g_done;

__device__ __forceinline__ float ex2f(float x){ float y; asm("ex2.approx.f32 %0,%1;":"=f"(y):"f"(x)); return y; }
__device__ __forceinline__ float lg2f(float x){ float y; asm("lg2.approx.f32 %0,%1;":"=f"(y):"f"(x)); return y; }
__device__ __forceinline__ float rcpf(float x){ float y; asm("rcp.approx.f32 %0,%1;":"=f"(y):"f"(x)); return y; }

// ---------------- K1: full match precompute ----------------
// Writes: g_meta (per-anchor class {-2 bg, -1 ignore, m pos}), g_gt_key (per-gt best
// anchor via atomicMax on packed key), g_labm (label bitmasks), g_w (CB weights).
__global__ void __launch_bounds__(256) k1_match(const float* __restrict__ gt_boxes,
                                                const int* __restrict__ counts,
                                                const float* __restrict__ anchors,
                                                const int* __restrict__ cls_num_list,
                                                const float* __restrict__ gt_labels) {
    int f = blockIdx.y;
    int tid = threadIdx.x;
    int lane = tid & 31, wrp = tid >> 5;
    __shared__ float4 sgtb[MM];
    __shared__ float  sga[MM];
    __shared__ unsigned long long skey_s[8][MM];
    __shared__ float  sraw[256];
    if (tid < MM) {
        float4 b = ((const float4*)gt_boxes)[f * MM + tid];
        sgtb[tid] = b;
        sga[tid] = (b.z - b.x) * (b.w - b.y);
    }
    __syncthreads();
    int count = counts[f]; if (count > MM) count = MM;

    float    bI[MM];
    unsigned bX[MM];
#pragma unroll
    for (int m = 0; m < MM; m++) { bI[m] = -1.f; bX[m] = 0; }

    for (int a = blockIdx.x * 256 + tid; a < AA; a += K1B * 256) {
        float4 an = ((const float4*)anchors)[a];
        float ax1 = an.x - 0.5f * an.z, ay1 = an.y - 0.5f * an.w;
        float ax2 = an.x + 0.5f * an.z, ay2 = an.y + 0.5f * an.w;
        float sa = an.z * an.w;
        float aB = -1.f;
        int   aM = 0;
#pragma unroll
        for (int m = 0; m < MM; m++) {
            if (m < count) {
                float4 b = sgtb[m];
                float lx = fmaxf(ax1, b.x), ly = fmaxf(ay1, b.y);
                float rx = fminf(ax2, b.z), ry = fminf(ay2, b.w);
                float w = fmaxf(rx - lx, 0.f), h = fmaxf(ry - ly, 0.f);
                float inter = w * h;
                float uni = sa + sga[m] - inter;
                // rational argmax: divide only on improvement; strict > = first-index tie
                bool upA = inter > aB * uni;
                bool upG = inter > bI[m] * uni;
                if (upA | upG) {
                    float q = inter / (uni + 1e-10f);
                    if (upA) { aB = q; aM = m; }
                    if (upG) { bI[m] = q; bX[m] = (unsigned)a; }
                }
            }
        }
        int meta = (count == 0) ? -1 : ((aB < 0.4f) ? -2 : ((aB < 0.5f) ? -1 : aM));
        g_meta[f * AA + a] = (signed char)meta;
    }

    // per-gt best anchor: warp shuffle max on packed (iou_bits, ~idx), then atomicMax
#pragma unroll
    for (int m = 0; m < MM; m++) {
        unsigned long long key = 0ull;
        if (m < count && bI[m] >= 0.f) {
            key = ((unsigned long long)__float_as_uint(bI[m]) << 32) |
                  (unsigned long long)(0xFFFFFFFFu - bX[m]);   // smaller idx wins ties
        }
#pragma unroll
        for (int o = 16; o > 0; o >>= 1) {
            unsigned long long other = __shfl_down_sync(0xffffffffu, key, o);
            if (other > key) key = other;
        }
        if (lane == 0) skey_s[wrp][m] = key;
    }
    __syncthreads();
    if (tid < MM) {
        unsigned long long k = skey_s[0][tid];
#pragma unroll
        for (int w = 1; w < 8; w++) { unsigned long long o = skey_s[w][tid]; if (o > k) k = o; }
        if (k) atomicMax(&g_gt_key[f * MM + tid], k);
    }

    if (blockIdx.x == 0) {
        // label bitmasks for this frame (once per frame, not once per k3 block)
        const float* gl = gt_labels + (size_t)f * MM * CC;
        for (int m = wrp; m < MM; m += 8) {
            unsigned b0 = __ballot_sync(0xffffffffu, gl[m * CC + lane] > 0.5f);
            unsigned b1 = __ballot_sync(0xffffffffu, gl[m * CC + 32 + lane] > 0.5f);
            unsigned b2 = __ballot_sync(0xffffffffu, (lane < (CC - 64)) ? (gl[m * CC + 64 + lane] > 0.5f) : false);
            if (lane == 0) {
                g_labm[(f * MM + m) * 3]     = b0;
                g_labm[(f * MM + m) * 3 + 1] = b1;
                g_labm[(f * MM + m) * 3 + 2] = b2;
            }
        }
        // class-balance weights (block (0,0) only)
        if (f == 0) {
            float raw = 0.f;
            if (tid < CC) {
                double beta = (double)0.9999f;
                double n = (double)cls_num_list[tid];
                raw = (float)((1.0 - beta) / (1.0 - pow(beta, n)));
            }
            sraw[tid] = raw;
            __syncthreads();
            for (int s = 128; s > 0; s >>= 1) {
                if (tid < s) sraw[tid] += sraw[tid + s];
                __syncthreads();
            }
            if (tid < CC) g_w[tid] = raw / sraw[0];
        }
    }
}

// ---------------- K3: loss accumulation + last-block finalize ----------------
__global__ void __launch_bounds__(256) k3_main(const float* __restrict__ confidence,
                                               const float* __restrict__ pred_loc,
                                               const float* __restrict__ gt_boxes,
                                               const int* __restrict__ counts,
                                               const float* __restrict__ anchors,
                                               const float* __restrict__ ego_preds,
                                               const int* __restrict__ ego_labels,
                                               float* __restrict__ out, int out_size) {
    int f = blockIdx.y;
    int ab = blockIdx.x * TA;
    int tid = threadIdx.x;
    int lane = tid & 31, wrp = tid >> 5;

    __shared__ unsigned labm_s[MM * 3];
    __shared__ float  w_s[CC];
    __shared__ signed char meta_s[TA];
    __shared__ int    sidx_s[MM];
    __shared__ float4 gtb_s[MM];
    __shared__ float  redc[8], redr[8], redp[8];
    __shared__ int    sflag;
    __shared__ float  col_s[CE];
    __shared__ int    nval_s;

    int count = counts[f]; if (count > MM) count = MM;

    if (tid < MM * 3) labm_s[tid] = g_labm[f * MM * 3 + tid];
    if (tid < CC) w_s[tid] = g_w[tid];
    if (tid < MM) {
        gtb_s[tid] = ((const float4*)gt_boxes)[f * MM + tid];
        int sidx = -1;
        if (tid < count) {
            unsigned long long key = g_gt_key[f * MM + tid];
            sidx = (int)(0xFFFFFFFFu - (unsigned)(key & 0xFFFFFFFFull));
        }
        sidx_s[tid] = sidx;
    }
    int meta = -1;
    if (tid < TA) meta = (int)g_meta[f * AA + ab + tid];
    __syncthreads();

    float myreg = 0.f, mypos = 0.f;
    if (tid < TA) {
        int a = ab + tid;
        for (int m = 0; m < count; m++)          // ascending: last write wins (ref scatter)
            if (sidx_s[m] == a) meta = m;
        meta_s[tid] = (signed char)meta;
        if (meta >= 0) {
            mypos = 1.f;
            float4 an = ((const float4*)anchors)[a];
            float4 b = gtb_s[meta];
            float lcx = ((b.x + b.z) * 0.5f - an.x) / (0.1f * an.z);
            float lcy = ((b.y + b.w) * 0.5f - an.y) / (0.1f * an.w);
            float lw = logf(fmaxf(b.z - b.x, 1e-6f) / an.z) * 5.0f;
            float lh = logf(fmaxf(b.w - b.y, 1e-6f) / an.w) * 5.0f;
            float4 pl = ((const float4*)pred_loc)[f * AA + a];
            float n0 = fabsf(pl.x - lcx), n1 = fabsf(pl.y - lcy);
            float n2 = fabsf(pl.z - lw),  n3 = fabsf(pl.w - lh);
            const float SB = 1.f / 9.f;
            myreg  = (n0 < SB ? 4.5f * n0 * n0 : n0 - 0.5f * SB);
            myreg += (n1 < SB ? 4.5f * n1 * n1 : n1 - 0.5f * SB);
            myreg += (n2 < SB ? 4.5f * n2 * n2 : n2 - 0.5f * SB);
            myreg += (n3 < SB ? 4.5f * n3 * n3 : n3 - 0.5f * SB);
        }
    }
    __syncthreads();

    // ---- hot loop: TA anchors x 80 classes as float4 ----
    //   t = x*log2e, u = 2^t, v = 1+u, s = lg2(v), r = 1/v
    //   neg: ln2*s*(1-r)*1e-4     pos: w * ln2*(s-t)*r
    const float4* c4 = (const float4*)(confidence + ((size_t)f * AA + ab) * CC);
    const float L2E = 1.4426950408889634f;
    const float LN2 = 0.6931471805599453f;
    float nacc = 0.f, pacc = 0.f;
    for (int e = tid; e < TA * CC / 4; e += 256) {        // 4800 groups
        int a_l = (int)(((unsigned)e * 52429u) >> 20);    // e / 20
        int cbase = (e - a_l * 20) * 4;
        int m = (int)meta_s[a_l];
        if (m != -1) {
            float4 x4 = __ldcs(c4 + e);
            unsigned mbits = 0u;
            if (m >= 0) mbits = (labm_s[m * 3 + (cbase >> 5)] >> (cbase & 31)) & 0xFu;
            float xs[4] = {x4.x, x4.y, x4.z, x4.w};
#pragma unroll
            for (int j = 0; j < 4; j++) {
                float x = xs[j];
                float t = x * L2E;
                float u = ex2f(t);
                float v = 1.f + u;
                float s = lg2f(v);
                float r = rcpf(v);
                if ((mbits >> j) & 1) pacc = fmaf(w_s[cbase + j] * (s - t), r, pacc);
                else                  nacc = fmaf(s, 1.f - r, nacc);
            }
        }
    }
    const float CB1M = 1.0f - 0.9999f;
    float csum = LN2 * fmaf(CB1M, nacc, pacc);

    // ---- block reductions via shuffles, one atomic each ----
#pragma unroll
    for (int o = 16; o > 0; o >>= 1) {
        csum  += __shfl_down_sync(0xffffffffu, csum, o);
        myreg += __shfl_down_sync(0xffffffffu, myreg, o);
        mypos += __shfl_down_sync(0xffffffffu, mypos, o);
    }
    if (lane == 0) { redc[wrp] = csum; redr[wrp] = myreg; redp[wrp] = mypos; }
    __syncthreads();
    if (tid == 0) {
        float c = 0.f, r = 0.f, p = 0.f;
#pragma unroll
        for (int w = 0; w < 8; w++) { c += redc[w]; r += redr[w]; p += redp[w]; }
        atomicAdd(&g_cls_sum, (double)c);
        if (r != 0.f) atomicAdd(&g_reg_sum, (double)r);
        if (p != 0.f) atomicAdd(&g_pos_cnt, (int)(p + 0.5f));
    }

    // ---- last-block finalize: ego focal + output + accumulator reset ----
    __threadfence();
    if (tid == 0) {
        unsigned d = atomicAdd(&g_done, 1u);
        sflag = (d == (unsigned)(K3BLKS - 1));
    }
    __syncthreads();
    if (sflag) {
        if (tid < CE) col_s[tid] = 0.f;
        if (tid == 0) nval_s = 0;
        __syncthreads();
        if (tid < NF) {
            int l = ego_labels[tid];
            if (l > -1) { atomicAdd(&nval_s, 1); if (l < CE) col_s[l] = 1.f; }
        }
        __syncthreads();
        float term = 0.f;
        if (tid < NF * CE) {
            int i = tid / CE, c = tid - i * CE;
            if (ego_labels[i] > -1) {
                float x = ego_preds[tid];
                float ep = 1.f / (1.f + expf(-x));
                ep = fminf(fmaxf(ep, 1e-7f), 1.f - 1e-7f);
                float oh = col_s[c];
                float af = 0.25f * oh + 0.75f * (1.f - oh);
                float pt = ep * oh + (1.f - ep) * (1.f - oh);
                float bce = -(oh * logf(ep) + (1.f - oh) * log1pf(-ep));
                float omp = 1.f - pt;
                term = bce * af * omp * omp;
            }
        }
#pragma unroll
        for (int o = 16; o > 0; o >>= 1) term += __shfl_down_sync(0xffffffffu, term, o);
        if (lane == 0) redc[wrp] = term;
        __syncthreads();
        if (tid == 0) {
            float esum = redc[0] + redc[1] + redc[2] + redc[3];
            int nval = nval_s;
            float ego = (nval > 0) ? esum / fmaxf((float)nval, 1.f) : 0.f;
            double cs = *((volatile double*)&g_cls_sum);
            double rs = *((volatile double*)&g_reg_sum);
            int pc = *((volatile int*)&g_pos_cnt);
            float np = fmaxf(1.f, (float)pc);
            float reg = (float)rs / (np * 4.f);
            float cls = (float)cs / np;
            if (out_size > 0) out[0] = reg;
            if (out_size > 1) out[1] = cls * 0.125f + ego * 0.25f;
            // reset for next graph replay
            g_cls_sum = 0.0;
            g_reg_sum = 0.0;
            g_pos_cnt = 0;
        }
        // reset per-gt keys (atomicMax target) for next replay
        for (int i = tid; i < NF * MM; i += 256) g_gt_key[i] = 0ull;
        __syncthreads();
        if (tid == 0) { __threadfence(); g_done = 0; }
    }
}

extern "C" void kernel_launch(void* const* d_in, const int* in_sizes, int n_in,
                              void* d_out, int out_size) {
    (void)in_sizes; (void)n_in;
    const float* confidence   = (const float*)d_in[0];
    const float* pred_loc     = (const float*)d_in[1];
    const float* gt_boxes     = (const float*)d_in[2];
    const float* gt_labels    = (const float*)d_in[3];
    const int*   counts       = (const int*)d_in[4];
    const float* anchors      = (const float*)d_in[5];
    const float* ego_preds    = (const float*)d_in[6];
    const int*   ego_labels   = (const int*)d_in[7];
    const int*   cls_num_list = (const int*)d_in[8];
    float* out = (float*)d_out;

    k1_match<<<dim3(K1B, NF), 256>>>(gt_boxes, counts, anchors, cls_num_list, gt_labels);
    k3_main<<<dim3(K3GX, NF), 256>>>(confidence, pred_loc, gt_boxes, counts, anchors,
                                     ego_preds, ego_labels, out, out_size);
}